// round 2
// baseline (speedup 1.0000x reference)
#include <cuda_runtime.h>
#include <math.h>

#define BB 4
#define NN 4096
#define MM 4096
#define CCH 64
#define KK 32
#define RADIUS 0.1f
#define RAD2 0.01f
#define EPSV 1e-5f

typedef unsigned long long u64;

// packed f32x2 helpers (sm_103a FFMA2 path)
__device__ __forceinline__ u64 pk2(float w) {
    u64 r; asm("mov.b64 %0, {%1, %1};" : "=l"(r) : "f"(w)); return r;
}
#define FMA2(d, a, b) asm("fma.rn.f32x2 %0, %1, %2, %0;" : "+l"(d) : "l"(a), "l"(b))
#define UNPK(lo, hi, v) asm("mov.b64 {%0, %1}, %2;" : "=f"(lo), "=f"(hi) : "l"(v))

// ---------------- device scratch ----------------
__device__ float    g_featT[BB * MM * CCH];
__device__ int      g_idx[BB * NN * KK];
__device__ unsigned g_nbr[BB * NN];
__device__ int      g_idxnn[BB * NN];

// ---------------- kernel 0: transpose ----------------
__global__ void k_transpose(const float* __restrict__ f) {
    int i = blockIdx.x * blockDim.x + threadIdx.x;
    if (i < BB * MM * CCH) {
        int c = i & 63;
        int m = (i >> 6) & (MM - 1);
        int b = i >> 18;
        g_featT[i] = f[(b * CCH + c) * MM + m];
    }
}

// ---------------- kernel 1: warp-bitonic top-K ----------------
__device__ __forceinline__ void bsort32(float& d, int& ix, int lane) {
#pragma unroll
    for (int k = 2; k <= 32; k <<= 1) {
#pragma unroll
        for (int j = k >> 1; j > 0; j >>= 1) {
            float od = __shfl_xor_sync(0xffffffffu, d, j);
            int   oi = __shfl_xor_sync(0xffffffffu, ix, j);
            bool keepMin = (((lane & k) == 0) == ((lane & j) == 0));
            bool take = keepMin ? (od < d) : (od > d);
            if (take) { d = od; ix = oi; }
        }
    }
}
__device__ __forceinline__ void bmerge32(float& d, int& ix, int lane) {
#pragma unroll
    for (int j = 16; j > 0; j >>= 1) {
        float od = __shfl_xor_sync(0xffffffffu, d, j);
        int   oi = __shfl_xor_sync(0xffffffffu, ix, j);
        bool keepMin = ((lane & j) == 0);
        bool take = keepMin ? (od < d) : (od > d);
        if (take) { d = od; ix = oi; }
    }
}

__global__ __launch_bounds__(256) void k_knn(const float* __restrict__ qxyz,
                                             const float* __restrict__ sxyz,
                                             const int* __restrict__ smask) {
    __shared__ float sx[MM], sy[MM], sz[MM];
    int b   = blockIdx.x >> 9;
    int grp = blockIdx.x & 511;
    for (int i = threadIdx.x; i < MM; i += 256) {
        bool v = smask[b * MM + i] > 0;
        float x = sxyz[(b * MM + i) * 3 + 0];
        float y = sxyz[(b * MM + i) * 3 + 1];
        float z = sxyz[(b * MM + i) * 3 + 2];
        sx[i] = v ? x : 1e18f;
        sy[i] = v ? y : 1e18f;
        sz[i] = v ? z : 1e18f;
    }
    __syncthreads();

    int warp = threadIdx.x >> 5, lane = threadIdx.x & 31;
    int n  = grp * 8 + warp;
    int qi = b * NN + n;
    float qx = qxyz[qi * 3 + 0];
    float qy = qxyz[qi * 3 + 1];
    float qz = qxyz[qi * 3 + 2];

    float bd = INFINITY; int bi = 0;
    float thr = INFINITY;
    for (int ch = 0; ch < MM / 32; ++ch) {
        int m = ch * 32 + lane;
        float dx = qx - sx[m], dy = qy - sy[m], dz = qz - sz[m];
        float d2 = fmaf(dx, dx, fmaf(dy, dy, dz * dz));
        if (__ballot_sync(0xffffffffu, d2 < thr)) {
            float nd = d2; int ni = m;
            bsort32(nd, ni, lane);
            float rd = __shfl_sync(0xffffffffu, nd, 31 ^ lane);
            int   ri = __shfl_sync(0xffffffffu, ni, 31 ^ lane);
            if (rd < bd) { bd = rd; bi = ri; }
            bmerge32(bd, bi, lane);
            thr = __shfl_sync(0xffffffffu, bd, 31);
        }
    }
    g_idx[qi * KK + lane] = bi;
    unsigned nb = __ballot_sync(0xffffffffu, bd <= RAD2);
    if (lane == 0) { g_nbr[qi] = nb; g_idxnn[qi] = bi; }
}

// ---------------- kernel 2: fused MLPs (FFMA2) ----------------
struct P2 {
    const float *qxyz, *sxyz;
    const int   *qmask;
    const float *Wth1, *bth1, *Wth2, *bth2;
    const float *Wphi, *bphi, *Wpsi, *bpsi, *Wal, *bal;
    const float *Wg1, *bg1, *Wg2, *bg2;
    const float *gt, *bet, *rmt, *rvt, *gg, *beg, *rmg, *rvg;
    float* out;
};

#define STRD 36
#define WS   68

constexpr int OFF_WPSI = 0;
constexpr int OFF_WAL  = 4352;
constexpr int OFF_WG1  = 8704;
constexpr int OFF_WG2  = 13056;
constexpr int OFF_WPHI = 17408;
constexpr int OFF_WEFF = 21760;   // 64*4 : [c][0..2]=W_eff, [c][3]=b_eff
constexpr int OFF_BIAS = 22016;   // 5*64 : phi, psi, al, g1, g2
constexpr int OFF_BN   = 22336;   // 4*64
constexpr int OFF_Q    = 22592;
constexpr int QO_XJ = 0, QO_R = 2304, QO_U = 4608;
constexpr int QO_POS = 6912, QO_FM = 7008, QO_XI = 7040, QO_RED = 7104, QO_KIDX = 7872;
constexpr int QSZ = 7904;
constexpr int SMEM_FLOATS = OFF_Q + 2 * QSZ;   // 38400 floats = 153600 B

__global__ __launch_bounds__(512, 1) void k_main(P2 p) {
    extern __shared__ float sm[];
    int tid = threadIdx.x;

    // ---- init: weights row-major padded to WS, W_eff fold, biases, BN ----
    {
        const float* srcs[5] = {p.Wpsi, p.Wal, p.Wg1, p.Wg2, p.Wphi};
        const int    offs[5] = {OFF_WPSI, OFF_WAL, OFF_WG1, OFF_WG2, OFF_WPHI};
#pragma unroll
        for (int w = 0; w < 5; ++w) {
            const float* s = srcs[w];
            float* d = sm + offs[w];
            for (int i = tid; i < 4096; i += 512) {
                int o = i >> 6, in = i & 63;
                d[o * WS + in] = s[i];
            }
        }
        // W_eff = W_theta2 @ W_theta1  (linear composition, no activation between)
        if (tid < 192) {
            int c = tid / 3, j = tid - 3 * c;
            float acc = 0.f;
            for (int c2 = 0; c2 < 64; ++c2)
                acc = fmaf(p.Wth2[c * 64 + c2], p.Wth1[c2 * 3 + j], acc);
            sm[OFF_WEFF + c * 4 + j] = acc;
        } else if (tid < 256) {
            int c = tid - 192;
            float acc = p.bth2[c];
            for (int c2 = 0; c2 < 64; ++c2)
                acc = fmaf(p.Wth2[c * 64 + c2], p.bth1[c2], acc);
            sm[OFF_WEFF + c * 4 + 3] = acc;
        } else if (tid < 320) {
            int i = tid - 256;
            sm[OFF_BIAS + 0 * 64 + i] = p.bphi[i];
            sm[OFF_BIAS + 1 * 64 + i] = p.bpsi[i];
            sm[OFF_BIAS + 2 * 64 + i] = p.bal[i];
            sm[OFF_BIAS + 3 * 64 + i] = p.bg1[i];
            sm[OFF_BIAS + 4 * 64 + i] = p.bg2[i];
            float it = p.gt[i] * rsqrtf(p.rvt[i] + EPSV);
            sm[OFF_BN + 0 * 64 + i] = it;
            sm[OFF_BN + 1 * 64 + i] = p.bet[i] - p.rmt[i] * it;
            float ig = p.gg[i] * rsqrtf(p.rvg[i] + EPSV);
            sm[OFF_BN + 2 * 64 + i] = ig;
            sm[OFF_BN + 3 * 64 + i] = p.beg[i] - p.rmg[i] * ig;
        }
    }
    __syncthreads();

    int q  = tid >> 8;
    int t  = tid & 255;
    int c  = t & 63;
    int g  = t >> 6;
    int k0 = g * 8;

    float* Q    = sm + OFF_Q + q * QSZ;
    float* xjB  = Q + QO_XJ;
    float* RB   = Q + QO_R;
    float* UB   = Q + QO_U;
    float* posB = Q + QO_POS;
    float* fmB  = Q + QO_FM;
    float* xiB  = Q + QO_XI;
    float* red  = Q + QO_RED;     // [0:256) lin_i / mx, [256:512) se, [512:768) sf
    int*   kidx = (int*)(Q + QO_KIDX);

    float b_phi = sm[OFF_BIAS + 0 * 64 + c];
    float b_psi = sm[OFF_BIAS + 1 * 64 + c];
    float b_al  = sm[OFF_BIAS + 2 * 64 + c];
    float b_g1  = sm[OFF_BIAS + 3 * 64 + c];
    float b_g2  = sm[OFF_BIAS + 4 * 64 + c];
    float inv_t = sm[OFF_BN + 0 * 64 + c];
    float sh_t  = sm[OFF_BN + 1 * 64 + c];
    float inv_g = sm[OFF_BN + 2 * 64 + c];
    float sh_g  = sm[OFF_BN + 3 * 64 + c];
    float we0   = sm[OFF_WEFF + c * 4 + 0];
    float we1   = sm[OFF_WEFF + c * 4 + 1];
    float we2   = sm[OFF_WEFF + c * 4 + 2];
    float beff  = sm[OFF_WEFF + c * 4 + 3];
    u64 bg12 = pk2(b_g1);

    const int npairs = (BB * NN) / 2;
    for (int pair = blockIdx.x; pair < npairs; pair += gridDim.x) {
        int qi = pair * 2 + q;
        int b  = qi >> 12;
        int n  = qi & (NN - 1);

        // ---- setup ----
        if (t < 32) {
            int k  = t;
            int ki = g_idx[qi * KK + k];
            kidx[k] = ki;
            float qx = p.qxyz[qi * 3 + 0];
            float qy = p.qxyz[qi * 3 + 1];
            float qz = p.qxyz[qi * 3 + 2];
            const float* s = p.sxyz + ((long)b * MM + ki) * 3;
            posB[0 * 32 + k] = (s[0] - qx) * (1.0f / RADIUS);
            posB[1 * 32 + k] = (s[1] - qy) * (1.0f / RADIUS);
            posB[2 * 32 + k] = (s[2] - qz) * (1.0f / RADIUS);
            unsigned nb = g_nbr[qi];
            int qm = p.qmask[qi];
            fmB[k] = (float)((nb >> k) & 1u) + (1.0f - (float)qm);
        } else if (t < 96) {
            int cc = t - 32;
            xiB[cc] = g_featT[((long)b * MM + g_idxnn[qi]) * 64 + cc];
        }
        __syncthreads();   // S1

        // ---- gather x_j + lin_i partials ----
        for (int i = t; i < 2048; i += 256) {
            int cc = i & 63, k = i >> 6;
            xjB[cc * STRD + k] = g_featT[((long)b * MM + kidx[k]) * 64 + cc];
        }
        {
            float acc = 0.f;
            const float* Wp = sm + OFF_WPHI + c * WS + g * 16;
#pragma unroll
            for (int c2 = 0; c2 < 16; ++c2)
                acc = fmaf(Wp[c2], xiB[g * 16 + c2], acc);
            red[g * 64 + c] = acc;
        }
        __syncthreads();   // S2

        float lin_i = red[c] + red[64 + c] + red[128 + c] + red[192 + c] + b_phi;

        // ---- stage A: psi(x_j), alpha(x_j) via FFMA2 ----
        u64 lj2[4] = {0, 0, 0, 0}, af2[4] = {0, 0, 0, 0};
        {
            const float* Wp = sm + OFF_WPSI + c * WS;
            const float* Wa = sm + OFF_WAL + c * WS;
            const float* xb = xjB + k0;
#pragma unroll 4
            for (int cq = 0; cq < 64; cq += 4) {
                float4 wp4 = *(const float4*)(Wp + cq);
                float4 wa4 = *(const float4*)(Wa + cq);
                const float* x0p = xb + cq * STRD;
#define ASTEP(WPV, WAV, J) { \
                u64 wp2 = pk2(WPV), wa2 = pk2(WAV); \
                ulonglong2 xa = *(const ulonglong2*)(x0p + (J) * STRD); \
                ulonglong2 xc = *(const ulonglong2*)(x0p + (J) * STRD + 4); \
                FMA2(lj2[0], wp2, xa.x); FMA2(lj2[1], wp2, xa.y); \
                FMA2(lj2[2], wp2, xc.x); FMA2(lj2[3], wp2, xc.y); \
                FMA2(af2[0], wa2, xa.x); FMA2(af2[1], wa2, xa.y); \
                FMA2(af2[2], wa2, xc.x); FMA2(af2[3], wa2, xc.y); }
                ASTEP(wp4.x, wa4.x, 0)
                ASTEP(wp4.y, wa4.y, 1)
                ASTEP(wp4.z, wa4.z, 2)
                ASTEP(wp4.w, wa4.w, 3)
#undef ASTEP
            }
        }
        float lj[8], af[8];
#pragma unroll
        for (int i = 0; i < 4; ++i) {
            UNPK(lj[2 * i], lj[2 * i + 1], lj2[i]);
            UNPK(af[2 * i], af[2 * i + 1], af2[i]);
        }
        float ft[8];
        {
            float4 rv0, rv1;
            float* rvp = &rv0.x;
#pragma unroll
            for (int kk = 0; kk < 8; ++kk) {
                int k = k0 + kk;
                float dpre = beff;
                dpre = fmaf(we0, posB[0 * 32 + k], dpre);
                dpre = fmaf(we1, posB[1 * 32 + k], dpre);
                dpre = fmaf(we2, posB[2 * 32 + k], dpre);
                float dl = fmaxf(fmaf(dpre, inv_t, sh_t), 0.f);
                float rel = lin_i - (lj[kk] + b_psi) + dl;
                ft[kk] = (af[kk] + b_al + dl) * fmB[k];
                if (kk < 4) (&rv0.x)[kk] = rel; else (&rv1.x)[kk - 4] = rel;
            }
            (void)rvp;
            *(float4*)(RB + c * STRD + k0) = rv0;
            *(float4*)(RB + c * STRD + k0 + 4) = rv1;
        }
        __syncthreads();   // S3

        // ---- stage B: u = gamma1(rel) + b_g1 ----
        u64 u2[4] = {0, 0, 0, 0};
        {
            const float* W  = sm + OFF_WG1 + c * WS;
            const float* rb = RB + k0;
#pragma unroll 4
            for (int cq = 0; cq < 64; cq += 4) {
                float4 w4 = *(const float4*)(W + cq);
                const float* r0p = rb + cq * STRD;
#define BSTEP(WV, J) { \
                u64 w2 = pk2(WV); \
                ulonglong2 ra = *(const ulonglong2*)(r0p + (J) * STRD); \
                ulonglong2 rc = *(const ulonglong2*)(r0p + (J) * STRD + 4); \
                FMA2(u2[0], w2, ra.x); FMA2(u2[1], w2, ra.y); \
                FMA2(u2[2], w2, rc.x); FMA2(u2[3], w2, rc.y); }
                BSTEP(w4.x, 0) BSTEP(w4.y, 1) BSTEP(w4.z, 2) BSTEP(w4.w, 3)
#undef BSTEP
            }
        }
#pragma unroll
        for (int i = 0; i < 4; ++i) {
            asm("add.rn.f32x2 %0, %0, %1;" : "+l"(u2[i]) : "l"(bg12));
        }
        {
            ulonglong2* up = (ulonglong2*)(UB + c * STRD + k0);
            up[0] = make_ulonglong2(u2[0], u2[1]);
            up[1] = make_ulonglong2(u2[2], u2[3]);
        }
        __syncthreads();   // S4

        // ---- stage C: rel2 = relu(bn(gamma2(u))) ----
        u64 v2[4] = {0, 0, 0, 0};
        {
            const float* W  = sm + OFF_WG2 + c * WS;
            const float* ub = UB + k0;
#pragma unroll 4
            for (int cq = 0; cq < 64; cq += 4) {
                float4 w4 = *(const float4*)(W + cq);
                const float* u0p = ub + cq * STRD;
#define CSTEP(WV, J) { \
                u64 w2 = pk2(WV); \
                ulonglong2 ua = *(const ulonglong2*)(u0p + (J) * STRD); \
                ulonglong2 uc = *(const ulonglong2*)(u0p + (J) * STRD + 4); \
                FMA2(v2[0], w2, ua.x); FMA2(v2[1], w2, ua.y); \
                FMA2(v2[2], w2, uc.x); FMA2(v2[3], w2, uc.y); }
                CSTEP(w4.x, 0) CSTEP(w4.y, 1) CSTEP(w4.z, 2) CSTEP(w4.w, 3)
#undef CSTEP
            }
        }
        float v[8];
#pragma unroll
        for (int i = 0; i < 4; ++i) UNPK(v[2 * i], v[2 * i + 1], v2[i]);
#pragma unroll
        for (int kk = 0; kk < 8; ++kk)
            v[kk] = fmaxf(fmaf(v[kk] + b_g2, inv_g, sh_g), 0.f);

        // ---- softmax over k (cross-g via smem) + weighted sum ----
        float mx = v[0];
#pragma unroll
        for (int kk = 1; kk < 8; ++kk) mx = fmaxf(mx, v[kk]);
        red[g * 64 + c] = mx;
        __syncthreads();   // S5
        float M = fmaxf(fmaxf(red[c], red[64 + c]), fmaxf(red[128 + c], red[192 + c]));
        float se = 0.f, sf = 0.f;
#pragma unroll
        for (int kk = 0; kk < 8; ++kk) {
            float e = __expf(v[kk] - M);
            se += e;
            sf = fmaf(e, ft[kk], sf);
        }
        red[256 + g * 64 + c] = se;
        red[512 + g * 64 + c] = sf;
        __syncthreads();   // S6
        if (g == 0) {
            float SE = red[256 + c] + red[320 + c] + red[384 + c] + red[448 + c];
            float SF = red[512 + c] + red[576 + c] + red[640 + c] + red[704 + c];
            p.out[((long)b * CCH + c) * NN + n] = SF / SE;
        }
        __syncthreads();   // S7 (protect red before next-iter reuse)
    }
}

// ---------------- host launcher ----------------
extern "C" void kernel_launch(void* const* d_in, const int* in_sizes, int n_in,
                              void* d_out, int out_size) {
    const float* qxyz  = (const float*)d_in[0];
    const float* sxyz  = (const float*)d_in[1];
    const int*   qmask = (const int*)d_in[2];
    const int*   smask = (const int*)d_in[3];
    const float* feat  = (const float*)d_in[4];

    P2 p;
    p.qxyz = qxyz; p.sxyz = sxyz; p.qmask = qmask;
    p.Wth1 = (const float*)d_in[5];  p.bth1 = (const float*)d_in[6];
    p.Wth2 = (const float*)d_in[7];  p.bth2 = (const float*)d_in[8];
    p.Wphi = (const float*)d_in[9];  p.bphi = (const float*)d_in[10];
    p.Wpsi = (const float*)d_in[11]; p.bpsi = (const float*)d_in[12];
    p.Wal  = (const float*)d_in[13]; p.bal  = (const float*)d_in[14];
    p.Wg1  = (const float*)d_in[15]; p.bg1  = (const float*)d_in[16];
    p.Wg2  = (const float*)d_in[17]; p.bg2  = (const float*)d_in[18];
    p.gt   = (const float*)d_in[19]; p.bet  = (const float*)d_in[20];
    p.rmt  = (const float*)d_in[21]; p.rvt  = (const float*)d_in[22];
    p.gg   = (const float*)d_in[23]; p.beg  = (const float*)d_in[24];
    p.rmg  = (const float*)d_in[25]; p.rvg  = (const float*)d_in[26];
    p.out  = (float*)d_out;

    k_transpose<<<(BB * MM * CCH + 255) / 256, 256>>>(feat);
    k_knn<<<(BB * NN) / 8, 256>>>(qxyz, sxyz, smask);

    cudaFuncSetAttribute(k_main, cudaFuncAttributeMaxDynamicSharedMemorySize,
                         SMEM_FLOATS * 4);
    int dev = 0, nsm = 148;
    cudaGetDevice(&dev);
    cudaDeviceGetAttribute(&nsm, cudaDevAttrMultiProcessorCount, dev);
    k_main<<<nsm, 512, SMEM_FLOATS * 4>>>(p);
}

// round 3
// speedup vs baseline: 1.5662x; 1.5662x over previous
#include <cuda_runtime.h>
#include <math.h>

#define BB 4
#define NN 4096
#define MM 4096
#define CCH 64
#define KK 32
#define RADIUS 0.1f
#define RAD2 0.01f
#define EPSV 1e-5f

// ---------------- device scratch ----------------
__device__ float    g_featT[BB * MM * CCH];
__device__ int      g_idx[BB * NN * KK];
__device__ unsigned g_nbr[BB * NN];
__device__ int      g_idxnn[BB * NN];

// ---------------- kernel 0: transpose ----------------
__global__ void k_transpose(const float* __restrict__ f) {
    int i = blockIdx.x * blockDim.x + threadIdx.x;
    if (i < BB * MM * CCH) {
        int c = i & 63;
        int m = (i >> 6) & (MM - 1);
        int b = i >> 18;
        g_featT[i] = f[(b * CCH + c) * MM + m];
    }
}

// ---------------- kernel 1: warp-bitonic top-K ----------------
__device__ __forceinline__ void bsort32(float& d, int& ix, int lane) {
#pragma unroll
    for (int k = 2; k <= 32; k <<= 1) {
#pragma unroll
        for (int j = k >> 1; j > 0; j >>= 1) {
            float od = __shfl_xor_sync(0xffffffffu, d, j);
            int   oi = __shfl_xor_sync(0xffffffffu, ix, j);
            bool keepMin = (((lane & k) == 0) == ((lane & j) == 0));
            bool take = keepMin ? (od < d) : (od > d);
            if (take) { d = od; ix = oi; }
        }
    }
}
__device__ __forceinline__ void bmerge32(float& d, int& ix, int lane) {
#pragma unroll
    for (int j = 16; j > 0; j >>= 1) {
        float od = __shfl_xor_sync(0xffffffffu, d, j);
        int   oi = __shfl_xor_sync(0xffffffffu, ix, j);
        bool keepMin = ((lane & j) == 0);
        bool take = keepMin ? (od < d) : (od > d);
        if (take) { d = od; ix = oi; }
    }
}

__global__ __launch_bounds__(256) void k_knn(const float* __restrict__ qxyz,
                                             const float* __restrict__ sxyz,
                                             const int* __restrict__ smask) {
    __shared__ float sx[MM], sy[MM], sz[MM];
    int b   = blockIdx.x >> 9;
    int grp = blockIdx.x & 511;
    for (int i = threadIdx.x; i < MM; i += 256) {
        bool v = smask[b * MM + i] > 0;
        float x = sxyz[(b * MM + i) * 3 + 0];
        float y = sxyz[(b * MM + i) * 3 + 1];
        float z = sxyz[(b * MM + i) * 3 + 2];
        sx[i] = v ? x : 1e18f;
        sy[i] = v ? y : 1e18f;
        sz[i] = v ? z : 1e18f;
    }
    __syncthreads();

    int warp = threadIdx.x >> 5, lane = threadIdx.x & 31;
    int n  = grp * 8 + warp;
    int qi = b * NN + n;
    float qx = qxyz[qi * 3 + 0];
    float qy = qxyz[qi * 3 + 1];
    float qz = qxyz[qi * 3 + 2];

    float bd = INFINITY; int bi = 0;
    float thr = INFINITY;
    for (int ch = 0; ch < MM / 32; ++ch) {
        int m = ch * 32 + lane;
        float dx = qx - sx[m], dy = qy - sy[m], dz = qz - sz[m];
        float d2 = fmaf(dx, dx, fmaf(dy, dy, dz * dz));
        if (__ballot_sync(0xffffffffu, d2 < thr)) {
            float nd = d2; int ni = m;
            bsort32(nd, ni, lane);
            float rd = __shfl_sync(0xffffffffu, nd, 31 ^ lane);
            int   ri = __shfl_sync(0xffffffffu, ni, 31 ^ lane);
            if (rd < bd) { bd = rd; bi = ri; }
            bmerge32(bd, bi, lane);
            thr = __shfl_sync(0xffffffffu, bd, 31);
        }
    }
    g_idx[qi * KK + lane] = bi;
    unsigned nb = __ballot_sync(0xffffffffu, bd <= RAD2);
    if (lane == 0) { g_nbr[qi] = nb; g_idxnn[qi] = bi; }
}

// ---------------- kernel 2: fused MLPs (scalar FFMA, theta-fold) ----------------
struct P2 {
    const float *qxyz, *sxyz;
    const int   *qmask;
    const float *Wth1, *bth1, *Wth2, *bth2;
    const float *Wphi, *bphi, *Wpsi, *bpsi, *Wal, *bal;
    const float *Wg1, *bg1, *Wg2, *bg2;
    const float *gt, *bet, *rmt, *rvt, *gg, *beg, *rmg, *rvg;
    float* out;
};

#define STRD 36

constexpr int OFF_WPSI = 0;
constexpr int OFF_WAL  = 4096;
constexpr int OFF_WG1  = 8192;
constexpr int OFF_WG2  = 12288;
constexpr int OFF_WPHI = 16384;
constexpr int OFF_WEFF = 20480;   // 64*4 : [c][0..2]=W_eff, [c][3]=b_eff
constexpr int OFF_BIAS = 20736;   // 5*64 : phi, psi, al, g1, g2
constexpr int OFF_BN   = 21056;   // 4*64
constexpr int OFF_Q    = 21312;
constexpr int QO_XJ = 0, QO_R = 2304, QO_U = 4608;
constexpr int QO_POS = 6912, QO_FM = 7008, QO_XI = 7040, QO_RED = 7104, QO_KIDX = 7872;
constexpr int QSZ = 7904;
constexpr int SMEM_FLOATS = OFF_Q + 2 * QSZ;   // 37120 floats = 148480 B

__global__ __launch_bounds__(512, 1) void k_main(P2 p) {
    extern __shared__ float sm[];
    int tid = threadIdx.x;

    // ---- init: weights column-major (Wt[in][out]), W_eff fold, biases, BN ----
    {
        const float* srcs[5] = {p.Wpsi, p.Wal, p.Wg1, p.Wg2, p.Wphi};
        const int    offs[5] = {OFF_WPSI, OFF_WAL, OFF_WG1, OFF_WG2, OFF_WPHI};
#pragma unroll
        for (int w = 0; w < 5; ++w) {
            const float* s = srcs[w];
            float* d = sm + offs[w];
            for (int i = tid; i < 4096; i += 512) {
                int o = i >> 6, in = i & 63;
                d[in * 64 + o] = s[i];
            }
        }
        // W_eff = W_theta2 @ W_theta1, b_eff = W_theta2 @ b_theta1 + b_theta2
        if (tid < 192) {
            int c = tid / 3, j = tid - 3 * c;
            float acc = 0.f;
            for (int c2 = 0; c2 < 64; ++c2)
                acc = fmaf(p.Wth2[c * 64 + c2], p.Wth1[c2 * 3 + j], acc);
            sm[OFF_WEFF + c * 4 + j] = acc;
        } else if (tid < 256) {
            int c = tid - 192;
            float acc = p.bth2[c];
            for (int c2 = 0; c2 < 64; ++c2)
                acc = fmaf(p.Wth2[c * 64 + c2], p.bth1[c2], acc);
            sm[OFF_WEFF + c * 4 + 3] = acc;
        } else if (tid < 320) {
            int i = tid - 256;
            sm[OFF_BIAS + 0 * 64 + i] = p.bphi[i];
            sm[OFF_BIAS + 1 * 64 + i] = p.bpsi[i];
            sm[OFF_BIAS + 2 * 64 + i] = p.bal[i];
            sm[OFF_BIAS + 3 * 64 + i] = p.bg1[i];
            sm[OFF_BIAS + 4 * 64 + i] = p.bg2[i];
            float it = p.gt[i] * rsqrtf(p.rvt[i] + EPSV);
            sm[OFF_BN + 0 * 64 + i] = it;
            sm[OFF_BN + 1 * 64 + i] = p.bet[i] - p.rmt[i] * it;
            float ig = p.gg[i] * rsqrtf(p.rvg[i] + EPSV);
            sm[OFF_BN + 2 * 64 + i] = ig;
            sm[OFF_BN + 3 * 64 + i] = p.beg[i] - p.rmg[i] * ig;
        }
    }
    __syncthreads();

    int q  = tid >> 8;
    int t  = tid & 255;
    int c  = t & 63;
    int g  = t >> 6;
    int k0 = g * 8;

    float* Q    = sm + OFF_Q + q * QSZ;
    float* xjB  = Q + QO_XJ;
    float* RB   = Q + QO_R;
    float* UB   = Q + QO_U;
    float* posB = Q + QO_POS;
    float* fmB  = Q + QO_FM;
    float* xiB  = Q + QO_XI;
    float* red  = Q + QO_RED;     // [0:256) lin_i/mx, [256:512) se, [512:768) sf
    int*   kidx = (int*)(Q + QO_KIDX);

    float b_phi = sm[OFF_BIAS + 0 * 64 + c];
    float b_psi = sm[OFF_BIAS + 1 * 64 + c];
    float b_al  = sm[OFF_BIAS + 2 * 64 + c];
    float b_g1  = sm[OFF_BIAS + 3 * 64 + c];
    float b_g2  = sm[OFF_BIAS + 4 * 64 + c];
    float inv_t = sm[OFF_BN + 0 * 64 + c];
    float sh_t  = sm[OFF_BN + 1 * 64 + c];
    float inv_g = sm[OFF_BN + 2 * 64 + c];
    float sh_g  = sm[OFF_BN + 3 * 64 + c];
    float we0   = sm[OFF_WEFF + c * 4 + 0];
    float we1   = sm[OFF_WEFF + c * 4 + 1];
    float we2   = sm[OFF_WEFF + c * 4 + 2];
    float beff  = sm[OFF_WEFF + c * 4 + 3];

    const int npairs = (BB * NN) / 2;
    for (int pair = blockIdx.x; pair < npairs; pair += gridDim.x) {
        int qi = pair * 2 + q;
        int b  = qi >> 12;
        int n  = qi & (NN - 1);

        // ---- setup ----
        if (t < 32) {
            int k  = t;
            int ki = g_idx[qi * KK + k];
            kidx[k] = ki;
            float qx = p.qxyz[qi * 3 + 0];
            float qy = p.qxyz[qi * 3 + 1];
            float qz = p.qxyz[qi * 3 + 2];
            const float* s = p.sxyz + ((long)b * MM + ki) * 3;
            posB[0 * 32 + k] = (s[0] - qx) * (1.0f / RADIUS);
            posB[1 * 32 + k] = (s[1] - qy) * (1.0f / RADIUS);
            posB[2 * 32 + k] = (s[2] - qz) * (1.0f / RADIUS);
            unsigned nb = g_nbr[qi];
            int qm = p.qmask[qi];
            fmB[k] = (float)((nb >> k) & 1u) + (1.0f - (float)qm);
        } else if (t < 96) {
            int cc = t - 32;
            xiB[cc] = g_featT[((long)b * MM + g_idxnn[qi]) * 64 + cc];
        }
        __syncthreads();   // S1

        // ---- gather x_j [64][32] + lin_i partials ----
        for (int i = t; i < 2048; i += 256) {
            int cc = i & 63, k = i >> 6;
            xjB[cc * STRD + k] = g_featT[((long)b * MM + kidx[k]) * 64 + cc];
        }
        {
            float acc = 0.f;
            const float* Wp = sm + OFF_WPHI;
#pragma unroll
            for (int c2 = 0; c2 < 16; ++c2)
                acc = fmaf(Wp[(g * 16 + c2) * 64 + c], xiB[g * 16 + c2], acc);
            red[g * 64 + c] = acc;
        }
        __syncthreads();   // S2

        float lin_i = red[c] + red[64 + c] + red[128 + c] + red[192 + c] + b_phi;

        // ---- stage A: psi(x_j), alpha(x_j) fused (theta folded out) ----
        float lj[8], af[8];
#pragma unroll
        for (int kk = 0; kk < 8; ++kk) { lj[kk] = 0.f; af[kk] = 0.f; }
        {
            const float* Wp = sm + OFF_WPSI + c;
            const float* Wa = sm + OFF_WAL + c;
            const float* xb = xjB + k0;
#pragma unroll 4
            for (int c2 = 0; c2 < 64; ++c2) {
                float wp = Wp[c2 * 64], wa = Wa[c2 * 64];
                float4 x0 = *(const float4*)(xb + c2 * STRD);
                float4 x1 = *(const float4*)(xb + c2 * STRD + 4);
                lj[0] = fmaf(wp, x0.x, lj[0]);  lj[1] = fmaf(wp, x0.y, lj[1]);
                lj[2] = fmaf(wp, x0.z, lj[2]);  lj[3] = fmaf(wp, x0.w, lj[3]);
                lj[4] = fmaf(wp, x1.x, lj[4]);  lj[5] = fmaf(wp, x1.y, lj[5]);
                lj[6] = fmaf(wp, x1.z, lj[6]);  lj[7] = fmaf(wp, x1.w, lj[7]);
                af[0] = fmaf(wa, x0.x, af[0]);  af[1] = fmaf(wa, x0.y, af[1]);
                af[2] = fmaf(wa, x0.z, af[2]);  af[3] = fmaf(wa, x0.w, af[3]);
                af[4] = fmaf(wa, x1.x, af[4]);  af[5] = fmaf(wa, x1.y, af[5]);
                af[6] = fmaf(wa, x1.z, af[6]);  af[7] = fmaf(wa, x1.w, af[7]);
            }
        }
        float ft[8];
        {
            float4 rv0, rv1;
#pragma unroll
            for (int kk = 0; kk < 8; ++kk) {
                int k = k0 + kk;
                float dpre = beff;
                dpre = fmaf(we0, posB[0 * 32 + k], dpre);
                dpre = fmaf(we1, posB[1 * 32 + k], dpre);
                dpre = fmaf(we2, posB[2 * 32 + k], dpre);
                float dl = fmaxf(fmaf(dpre, inv_t, sh_t), 0.f);
                float rel = lin_i - (lj[kk] + b_psi) + dl;
                ft[kk] = (af[kk] + b_al + dl) * fmB[k];
                if (kk < 4) (&rv0.x)[kk] = rel; else (&rv1.x)[kk - 4] = rel;
            }
            *(float4*)(RB + c * STRD + k0) = rv0;
            *(float4*)(RB + c * STRD + k0 + 4) = rv1;
        }
        __syncthreads();   // S3

        // ---- stage B: u = gamma1(rel) + b_g1 ----
        float u[8];
#pragma unroll
        for (int kk = 0; kk < 8; ++kk) u[kk] = 0.f;
        {
            const float* W  = sm + OFF_WG1 + c;
            const float* rb = RB + k0;
#pragma unroll 4
            for (int c2 = 0; c2 < 64; ++c2) {
                float w = W[c2 * 64];
                float4 r0 = *(const float4*)(rb + c2 * STRD);
                float4 r1 = *(const float4*)(rb + c2 * STRD + 4);
                u[0] = fmaf(w, r0.x, u[0]); u[1] = fmaf(w, r0.y, u[1]);
                u[2] = fmaf(w, r0.z, u[2]); u[3] = fmaf(w, r0.w, u[3]);
                u[4] = fmaf(w, r1.x, u[4]); u[5] = fmaf(w, r1.y, u[5]);
                u[6] = fmaf(w, r1.z, u[6]); u[7] = fmaf(w, r1.w, u[7]);
            }
        }
        {
            float4 uv0, uv1;
#pragma unroll
            for (int kk = 0; kk < 8; ++kk) {
                float uu = u[kk] + b_g1;
                if (kk < 4) (&uv0.x)[kk] = uu; else (&uv1.x)[kk - 4] = uu;
            }
            *(float4*)(UB + c * STRD + k0) = uv0;
            *(float4*)(UB + c * STRD + k0 + 4) = uv1;
        }
        __syncthreads();   // S4

        // ---- stage C: rel2 = relu(bn(gamma2(u))) ----
        float v[8];
#pragma unroll
        for (int kk = 0; kk < 8; ++kk) v[kk] = 0.f;
        {
            const float* W  = sm + OFF_WG2 + c;
            const float* ub = UB + k0;
#pragma unroll 4
            for (int c2 = 0; c2 < 64; ++c2) {
                float w = W[c2 * 64];
                float4 u0 = *(const float4*)(ub + c2 * STRD);
                float4 u1 = *(const float4*)(ub + c2 * STRD + 4);
                v[0] = fmaf(w, u0.x, v[0]); v[1] = fmaf(w, u0.y, v[1]);
                v[2] = fmaf(w, u0.z, v[2]); v[3] = fmaf(w, u0.w, v[3]);
                v[4] = fmaf(w, u1.x, v[4]); v[5] = fmaf(w, u1.y, v[5]);
                v[6] = fmaf(w, u1.z, v[6]); v[7] = fmaf(w, u1.w, v[7]);
            }
        }
#pragma unroll
        for (int kk = 0; kk < 8; ++kk)
            v[kk] = fmaxf(fmaf(v[kk] + b_g2, inv_g, sh_g), 0.f);

        // ---- softmax over k (cross-g via smem) + weighted sum ----
        float mx = v[0];
#pragma unroll
        for (int kk = 1; kk < 8; ++kk) mx = fmaxf(mx, v[kk]);
        red[g * 64 + c] = mx;
        __syncthreads();   // S5
        float M = fmaxf(fmaxf(red[c], red[64 + c]), fmaxf(red[128 + c], red[192 + c]));
        float se = 0.f, sf = 0.f;
#pragma unroll
        for (int kk = 0; kk < 8; ++kk) {
            float e = __expf(v[kk] - M);
            se += e;
            sf = fmaf(e, ft[kk], sf);
        }
        red[256 + g * 64 + c] = se;
        red[512 + g * 64 + c] = sf;
        __syncthreads();   // S6
        if (g == 0) {
            float SE = red[256 + c] + red[320 + c] + red[384 + c] + red[448 + c];
            float SF = red[512 + c] + red[576 + c] + red[640 + c] + red[704 + c];
            p.out[((long)b * CCH + c) * NN + n] = SF / SE;
        }
        __syncthreads();   // S7
    }
}

// ---------------- host launcher ----------------
extern "C" void kernel_launch(void* const* d_in, const int* in_sizes, int n_in,
                              void* d_out, int out_size) {
    const float* qxyz  = (const float*)d_in[0];
    const float* sxyz  = (const float*)d_in[1];
    const int*   qmask = (const int*)d_in[2];
    const int*   smask = (const int*)d_in[3];
    const float* feat  = (const float*)d_in[4];

    P2 p;
    p.qxyz = qxyz; p.sxyz = sxyz; p.qmask = qmask;
    p.Wth1 = (const float*)d_in[5];  p.bth1 = (const float*)d_in[6];
    p.Wth2 = (const float*)d_in[7];  p.bth2 = (const float*)d_in[8];
    p.Wphi = (const float*)d_in[9];  p.bphi = (const float*)d_in[10];
    p.Wpsi = (const float*)d_in[11]; p.bpsi = (const float*)d_in[12];
    p.Wal  = (const float*)d_in[13]; p.bal  = (const float*)d_in[14];
    p.Wg1  = (const float*)d_in[15]; p.bg1  = (const float*)d_in[16];
    p.Wg2  = (const float*)d_in[17]; p.bg2  = (const float*)d_in[18];
    p.gt   = (const float*)d_in[19]; p.bet  = (const float*)d_in[20];
    p.rmt  = (const float*)d_in[21]; p.rvt  = (const float*)d_in[22];
    p.gg   = (const float*)d_in[23]; p.beg  = (const float*)d_in[24];
    p.rmg  = (const float*)d_in[25]; p.rvg  = (const float*)d_in[26];
    p.out  = (float*)d_out;

    k_transpose<<<(BB * MM * CCH + 255) / 256, 256>>>(feat);
    k_knn<<<(BB * NN) / 8, 256>>>(qxyz, sxyz, smask);

    cudaFuncSetAttribute(k_main, cudaFuncAttributeMaxDynamicSharedMemorySize,
                         SMEM_FLOATS * 4);
    int dev = 0, nsm = 148;
    cudaGetDevice(&dev);
    cudaDeviceGetAttribute(&nsm, cudaDevAttrMultiProcessorCount, dev);
    k_main<<<nsm, 512, SMEM_FLOATS * 4>>>(p);
}

// round 4
// speedup vs baseline: 2.2987x; 1.4677x over previous
#include <cuda_runtime.h>
#include <math.h>

#define BB 4
#define NN 4096
#define MM 4096
#define CCH 64
#define KK 32
#define RADIUS 0.1f
#define RAD2 0.01f
#define EPSV 1e-5f

// ---------------- device scratch ----------------
__device__ float    g_featT[BB * MM * CCH];   // [B][M][C]
__device__ int      g_idx[BB * NN * KK];
__device__ unsigned g_nbr[BB * NN];
__device__ int      g_idxnn[BB * NN];
__device__ float    g_Wgeff[CCH * CCH];       // Wg2@Wg1  row-major [o][i]
__device__ float    g_Wqi[CCH * CCH];         // Wgeff@Wphi
__device__ float    g_Wqj[CCH * CCH];         // Wgeff@Wpsi
__device__ float    g_bconst[CCH];            // Wgeff@(bphi-bpsi) + Wg2@bg1 + bg2
__device__ float    g_Qi[BB * MM * CCH];      // per-support precomputed
__device__ float    g_Qj[BB * MM * CCH];
__device__ float    g_AF[BB * MM * CCH];

// ---------------- kernel 0: transpose ----------------
__global__ void k_transpose(const float* __restrict__ f) {
    int i = blockIdx.x * blockDim.x + threadIdx.x;
    if (i < BB * MM * CCH) {
        int c = i & 63;
        int m = (i >> 6) & (MM - 1);
        int b = i >> 18;
        g_featT[i] = f[(b * CCH + c) * MM + m];
    }
}

// ---------------- kernel 1: warp-bitonic top-K ----------------
__device__ __forceinline__ void bsort32(float& d, int& ix, int lane) {
#pragma unroll
    for (int k = 2; k <= 32; k <<= 1) {
#pragma unroll
        for (int j = k >> 1; j > 0; j >>= 1) {
            float od = __shfl_xor_sync(0xffffffffu, d, j);
            int   oi = __shfl_xor_sync(0xffffffffu, ix, j);
            bool keepMin = (((lane & k) == 0) == ((lane & j) == 0));
            bool take = keepMin ? (od < d) : (od > d);
            if (take) { d = od; ix = oi; }
        }
    }
}
__device__ __forceinline__ void bmerge32(float& d, int& ix, int lane) {
#pragma unroll
    for (int j = 16; j > 0; j >>= 1) {
        float od = __shfl_xor_sync(0xffffffffu, d, j);
        int   oi = __shfl_xor_sync(0xffffffffu, ix, j);
        bool keepMin = ((lane & j) == 0);
        bool take = keepMin ? (od < d) : (od > d);
        if (take) { d = od; ix = oi; }
    }
}

__global__ __launch_bounds__(256) void k_knn(const float* __restrict__ qxyz,
                                             const float* __restrict__ sxyz,
                                             const int* __restrict__ smask) {
    __shared__ float sx[MM], sy[MM], sz[MM];
    int b   = blockIdx.x >> 9;
    int grp = blockIdx.x & 511;
    for (int i = threadIdx.x; i < MM; i += 256) {
        bool v = smask[b * MM + i] > 0;
        float x = sxyz[(b * MM + i) * 3 + 0];
        float y = sxyz[(b * MM + i) * 3 + 1];
        float z = sxyz[(b * MM + i) * 3 + 2];
        sx[i] = v ? x : 1e18f;
        sy[i] = v ? y : 1e18f;
        sz[i] = v ? z : 1e18f;
    }
    __syncthreads();

    int warp = threadIdx.x >> 5, lane = threadIdx.x & 31;
    int n  = grp * 8 + warp;
    int qi = b * NN + n;
    float qx = qxyz[qi * 3 + 0];
    float qy = qxyz[qi * 3 + 1];
    float qz = qxyz[qi * 3 + 2];

    float bd = INFINITY; int bi = 0;
    float thr = INFINITY;
    for (int ch = 0; ch < MM / 32; ++ch) {
        int m = ch * 32 + lane;
        float dx = qx - sx[m], dy = qy - sy[m], dz = qz - sz[m];
        float d2 = fmaf(dx, dx, fmaf(dy, dy, dz * dz));
        if (__ballot_sync(0xffffffffu, d2 < thr)) {
            float nd = d2; int ni = m;
            bsort32(nd, ni, lane);
            float rd = __shfl_sync(0xffffffffu, nd, 31 ^ lane);
            int   ri = __shfl_sync(0xffffffffu, ni, 31 ^ lane);
            if (rd < bd) { bd = rd; bi = ri; }
            bmerge32(bd, bi, lane);
            thr = __shfl_sync(0xffffffffu, bd, 31);
        }
    }
    g_idx[qi * KK + lane] = bi;
    unsigned nb = __ballot_sync(0xffffffffu, bd <= RAD2);
    if (lane == 0) { g_nbr[qi] = nb; g_idxnn[qi] = bi; }
}

// ---------------- kernel 2: compose weight matrices ----------------
__global__ __launch_bounds__(256) void k_compose(
    const float* __restrict__ Wg1, const float* __restrict__ Wg2,
    const float* __restrict__ Wphi, const float* __restrict__ Wpsi,
    const float* __restrict__ bphi, const float* __restrict__ bpsi,
    const float* __restrict__ bg1, const float* __restrict__ bg2) {
    __shared__ float G[CCH * CCH];
    int tid = threadIdx.x;
    for (int e = tid; e < 4096; e += 256) {
        int o = e >> 6, i = e & 63;
        float a = 0.f;
        for (int c = 0; c < 64; ++c)
            a = fmaf(Wg2[o * 64 + c], Wg1[c * 64 + i], a);
        G[e] = a;
        g_Wgeff[e] = a;
    }
    __syncthreads();
    for (int e = tid; e < 4096; e += 256) {
        int o = e >> 6, i = e & 63;
        float qi = 0.f, qj = 0.f;
        for (int c = 0; c < 64; ++c) {
            float g = G[o * 64 + c];
            qi = fmaf(g, Wphi[c * 64 + i], qi);
            qj = fmaf(g, Wpsi[c * 64 + i], qj);
        }
        g_Wqi[e] = qi;
        g_Wqj[e] = qj;
    }
    if (tid < 64) {
        float a = bg2[tid];
        for (int c = 0; c < 64; ++c)
            a = fmaf(Wg2[tid * 64 + c], bg1[c], a);
        for (int i = 0; i < 64; ++i)
            a = fmaf(G[tid * 64 + i], bphi[i] - bpsi[i], a);
        g_bconst[tid] = a;
    }
}

// ---------------- kernel 3: per-support-point precompute ----------------
#define STRD 36
constexpr int PRE_WQI = 0, PRE_WQJ = 4096, PRE_WAL = 8192, PRE_X = 12288;
constexpr int PRE_SM = PRE_X + 64 * STRD;   // 14592 floats = 58368 B

__global__ __launch_bounds__(256) void k_pre(const float* __restrict__ Wal) {
    extern __shared__ float s[];
    int tid = threadIdx.x;
    for (int e = tid; e < 4096; e += 256) {
        int o = e >> 6, in = e & 63;
        s[PRE_WQI + in * 64 + o] = g_Wqi[e];
        s[PRE_WQJ + in * 64 + o] = g_Wqj[e];
        s[PRE_WAL + in * 64 + o] = Wal[e];
    }
    __syncthreads();

    int base = blockIdx.x * 32;                 // 512 blocks * 32 points
    int c = tid & 63, g = tid >> 6, k0 = g * 8;
    float* xS = s + PRE_X;
    for (int i = tid; i < 2048; i += 256) {
        int cc = i & 63, k = i >> 6;
        xS[cc * STRD + k] = g_featT[(long)(base + k) * 64 + cc];
    }
    __syncthreads();

    float qi[8], qj[8], af[8];
#pragma unroll
    for (int kk = 0; kk < 8; ++kk) { qi[kk] = 0.f; qj[kk] = 0.f; af[kk] = 0.f; }
    const float* Wi = s + PRE_WQI + c;
    const float* Wj = s + PRE_WQJ + c;
    const float* Wa = s + PRE_WAL + c;
    const float* xb = xS + k0;
#pragma unroll 4
    for (int c2 = 0; c2 < 64; ++c2) {
        float wi = Wi[c2 * 64], wj = Wj[c2 * 64], wa = Wa[c2 * 64];
        float4 x0 = *(const float4*)(xb + c2 * STRD);
        float4 x1 = *(const float4*)(xb + c2 * STRD + 4);
        qi[0] = fmaf(wi, x0.x, qi[0]); qi[1] = fmaf(wi, x0.y, qi[1]);
        qi[2] = fmaf(wi, x0.z, qi[2]); qi[3] = fmaf(wi, x0.w, qi[3]);
        qi[4] = fmaf(wi, x1.x, qi[4]); qi[5] = fmaf(wi, x1.y, qi[5]);
        qi[6] = fmaf(wi, x1.z, qi[6]); qi[7] = fmaf(wi, x1.w, qi[7]);
        qj[0] = fmaf(wj, x0.x, qj[0]); qj[1] = fmaf(wj, x0.y, qj[1]);
        qj[2] = fmaf(wj, x0.z, qj[2]); qj[3] = fmaf(wj, x0.w, qj[3]);
        qj[4] = fmaf(wj, x1.x, qj[4]); qj[5] = fmaf(wj, x1.y, qj[5]);
        qj[6] = fmaf(wj, x1.z, qj[6]); qj[7] = fmaf(wj, x1.w, qj[7]);
        af[0] = fmaf(wa, x0.x, af[0]); af[1] = fmaf(wa, x0.y, af[1]);
        af[2] = fmaf(wa, x0.z, af[2]); af[3] = fmaf(wa, x0.w, af[3]);
        af[4] = fmaf(wa, x1.x, af[4]); af[5] = fmaf(wa, x1.y, af[5]);
        af[6] = fmaf(wa, x1.z, af[6]); af[7] = fmaf(wa, x1.w, af[7]);
    }
#pragma unroll
    for (int kk = 0; kk < 8; ++kk) {
        long o = (long)(base + k0 + kk) * 64 + c;
        g_Qi[o] = qi[kk];
        g_Qj[o] = qj[kk];
        g_AF[o] = af[kk];
    }
}

// ---------------- kernel 4: fused per-query kernel ----------------
struct P2 {
    const float *qxyz, *sxyz;
    const int   *qmask;
    const float *Wth1, *bth1, *Wth2, *bth2;
    const float *bal;
    const float *gt, *bet, *rmt, *rvt, *gg, *beg, *rmg, *rvg;
    float* out;
};

constexpr int OFF_WG   = 0;       // WgeffT [in][out] 4096
constexpr int OFF_WEFF = 4096;    // 64*4 : theta fold
constexpr int OFF_CC   = 4352;    // bal(64) | bconst(64)
constexpr int OFF_BN   = 4480;    // 4*64
constexpr int OFF_Q    = 4736;
constexpr int QO_QJ = 0, QO_AF = 2304, QO_DL = 4608;
constexpr int QO_POS = 6912, QO_FM = 7008, QO_QI = 7040, QO_RED = 7104, QO_KIDX = 7872;
constexpr int QSZ = 7904;
constexpr int SMEM_FLOATS = OFF_Q + 2 * QSZ;   // 20544 floats = 82176 B

__global__ __launch_bounds__(512, 2) void k_main(P2 p) {
    extern __shared__ float sm[];
    int tid = threadIdx.x;

    // ---- init ----
    {
        for (int i = tid; i < 4096; i += 512) {
            int o = i >> 6, in = i & 63;
            sm[OFF_WG + in * 64 + o] = g_Wgeff[i];
        }
        if (tid < 192) {
            int c = tid / 3, j = tid - 3 * c;
            float acc = 0.f;
            for (int c2 = 0; c2 < 64; ++c2)
                acc = fmaf(p.Wth2[c * 64 + c2], p.Wth1[c2 * 3 + j], acc);
            sm[OFF_WEFF + c * 4 + j] = acc;
        } else if (tid < 256) {
            int c = tid - 192;
            float acc = p.bth2[c];
            for (int c2 = 0; c2 < 64; ++c2)
                acc = fmaf(p.Wth2[c * 64 + c2], p.bth1[c2], acc);
            sm[OFF_WEFF + c * 4 + 3] = acc;
        } else if (tid < 320) {
            int i = tid - 256;
            sm[OFF_CC + i]      = p.bal[i];
            sm[OFF_CC + 64 + i] = g_bconst[i];
            float it = p.gt[i] * rsqrtf(p.rvt[i] + EPSV);
            sm[OFF_BN + 0 * 64 + i] = it;
            sm[OFF_BN + 1 * 64 + i] = p.bet[i] - p.rmt[i] * it;
            float ig = p.gg[i] * rsqrtf(p.rvg[i] + EPSV);
            sm[OFF_BN + 2 * 64 + i] = ig;
            sm[OFF_BN + 3 * 64 + i] = p.beg[i] - p.rmg[i] * ig;
        }
    }
    __syncthreads();

    int q  = tid >> 8;
    int t  = tid & 255;
    int c  = t & 63;
    int g  = t >> 6;
    int k0 = g * 8;

    float* Q    = sm + OFF_Q + q * QSZ;
    float* QjB  = Q + QO_QJ;
    float* AFB  = Q + QO_AF;
    float* dlB  = Q + QO_DL;
    float* posB = Q + QO_POS;
    float* fmB  = Q + QO_FM;
    float* qiB  = Q + QO_QI;
    float* red  = Q + QO_RED;     // [0:256) mx, [256:512) se, [512:768) sf
    int*   kidx = (int*)(Q + QO_KIDX);

    float b_al  = sm[OFF_CC + c];
    float bcn   = sm[OFF_CC + 64 + c];
    float inv_t = sm[OFF_BN + 0 * 64 + c];
    float sh_t  = sm[OFF_BN + 1 * 64 + c];
    float inv_g = sm[OFF_BN + 2 * 64 + c];
    float sh_g  = sm[OFF_BN + 3 * 64 + c];
    float we0   = sm[OFF_WEFF + c * 4 + 0];
    float we1   = sm[OFF_WEFF + c * 4 + 1];
    float we2   = sm[OFF_WEFF + c * 4 + 2];
    float beff  = sm[OFF_WEFF + c * 4 + 3];

    const int npairs = (BB * NN) / 2;
    for (int pair = blockIdx.x; pair < npairs; pair += gridDim.x) {
        int qi = pair * 2 + q;
        int b  = qi >> 12;
        int n  = qi & (NN - 1);

        // ---- setup ----
        if (t < 32) {
            int k  = t;
            int ki = g_idx[qi * KK + k];
            kidx[k] = ki;
            float qx = p.qxyz[qi * 3 + 0];
            float qy = p.qxyz[qi * 3 + 1];
            float qz = p.qxyz[qi * 3 + 2];
            const float* s = p.sxyz + ((long)b * MM + ki) * 3;
            posB[0 * 32 + k] = (s[0] - qx) * (1.0f / RADIUS);
            posB[1 * 32 + k] = (s[1] - qy) * (1.0f / RADIUS);
            posB[2 * 32 + k] = (s[2] - qz) * (1.0f / RADIUS);
            unsigned nb = g_nbr[qi];
            int qm = p.qmask[qi];
            fmB[k] = (float)((nb >> k) & 1u) + (1.0f - (float)qm);
        } else if (t < 96) {
            int cc = t - 32;
            qiB[cc] = g_Qi[((long)b * MM + g_idxnn[qi]) * 64 + cc];
        }
        __syncthreads();   // S1

        // ---- gather Qj + AF rows, compute delta ----
        for (int i = t; i < 2048; i += 256) {
            int cc = i & 63, k = i >> 6;
            long o = ((long)b * MM + kidx[k]) * 64 + cc;
            QjB[cc * STRD + k] = g_Qj[o];
            AFB[cc * STRD + k] = g_AF[o];
        }
        float dl[8];
        {
            float4 d0, d1;
#pragma unroll
            for (int kk = 0; kk < 8; ++kk) {
                int k = k0 + kk;
                float dpre = beff;
                dpre = fmaf(we0, posB[0 * 32 + k], dpre);
                dpre = fmaf(we1, posB[1 * 32 + k], dpre);
                dpre = fmaf(we2, posB[2 * 32 + k], dpre);
                dl[kk] = fmaxf(fmaf(dpre, inv_t, sh_t), 0.f);
                if (kk < 4) (&d0.x)[kk] = dl[kk]; else (&d1.x)[kk - 4] = dl[kk];
            }
            *(float4*)(dlB + c * STRD + k0) = d0;
            *(float4*)(dlB + c * STRD + k0 + 4) = d1;
        }
        __syncthreads();   // S2

        // ---- matvec: acc = (Wgeff @ delta)[c][k0..k0+7] ----
        float acc[8];
#pragma unroll
        for (int kk = 0; kk < 8; ++kk) acc[kk] = 0.f;
        {
            const float* W  = sm + OFF_WG + c;
            const float* db = dlB + k0;
#pragma unroll 4
            for (int c2 = 0; c2 < 64; ++c2) {
                float w = W[c2 * 64];
                float4 d0 = *(const float4*)(db + c2 * STRD);
                float4 d1 = *(const float4*)(db + c2 * STRD + 4);
                acc[0] = fmaf(w, d0.x, acc[0]); acc[1] = fmaf(w, d0.y, acc[1]);
                acc[2] = fmaf(w, d0.z, acc[2]); acc[3] = fmaf(w, d0.w, acc[3]);
                acc[4] = fmaf(w, d1.x, acc[4]); acc[5] = fmaf(w, d1.y, acc[5]);
                acc[6] = fmaf(w, d1.z, acc[6]); acc[7] = fmaf(w, d1.w, acc[7]);
            }
        }

        // ---- epilogue: rel2, softmax, weighted sum ----
        float qic = qiB[c];
        float4 qj0 = *(const float4*)(QjB + c * STRD + k0);
        float4 qj1 = *(const float4*)(QjB + c * STRD + k0 + 4);
        float4 af0 = *(const float4*)(AFB + c * STRD + k0);
        float4 af1 = *(const float4*)(AFB + c * STRD + k0 + 4);
        float v[8], ft[8];
#pragma unroll
        for (int kk = 0; kk < 8; ++kk) {
            float qjv = (kk < 4) ? (&qj0.x)[kk] : (&qj1.x)[kk - 4];
            float afv = (kk < 4) ? (&af0.x)[kk] : (&af1.x)[kk - 4];
            float pre2 = qic - qjv + acc[kk] + bcn;
            v[kk] = fmaxf(fmaf(pre2, inv_g, sh_g), 0.f);
            ft[kk] = (afv + b_al + dl[kk]) * fmB[k0 + kk];
        }
        float mx = v[0];
#pragma unroll
        for (int kk = 1; kk < 8; ++kk) mx = fmaxf(mx, v[kk]);
        red[g * 64 + c] = mx;
        __syncthreads();   // S3
        float M = fmaxf(fmaxf(red[c], red[64 + c]), fmaxf(red[128 + c], red[192 + c]));
        float se = 0.f, sf = 0.f;
#pragma unroll
        for (int kk = 0; kk < 8; ++kk) {
            float e = __expf(v[kk] - M);
            se += e;
            sf = fmaf(e, ft[kk], sf);
        }
        red[256 + g * 64 + c] = se;
        red[512 + g * 64 + c] = sf;
        __syncthreads();   // S4
        if (g == 0) {
            float SE = red[256 + c] + red[320 + c] + red[384 + c] + red[448 + c];
            float SF = red[512 + c] + red[576 + c] + red[640 + c] + red[704 + c];
            p.out[((long)b * CCH + c) * NN + n] = SF / SE;
        }
        __syncthreads();   // S5
    }
}

// ---------------- host launcher ----------------
extern "C" void kernel_launch(void* const* d_in, const int* in_sizes, int n_in,
                              void* d_out, int out_size) {
    const float* qxyz  = (const float*)d_in[0];
    const float* sxyz  = (const float*)d_in[1];
    const int*   qmask = (const int*)d_in[2];
    const int*   smask = (const int*)d_in[3];
    const float* feat  = (const float*)d_in[4];
    const float* Wth1  = (const float*)d_in[5];
    const float* bth1  = (const float*)d_in[6];
    const float* Wth2  = (const float*)d_in[7];
    const float* bth2  = (const float*)d_in[8];
    const float* Wphi  = (const float*)d_in[9];
    const float* bphi  = (const float*)d_in[10];
    const float* Wpsi  = (const float*)d_in[11];
    const float* bpsi  = (const float*)d_in[12];
    const float* Wal   = (const float*)d_in[13];
    const float* bal   = (const float*)d_in[14];
    const float* Wg1   = (const float*)d_in[15];
    const float* bg1   = (const float*)d_in[16];
    const float* Wg2   = (const float*)d_in[17];
    const float* bg2   = (const float*)d_in[18];

    P2 p;
    p.qxyz = qxyz; p.sxyz = sxyz; p.qmask = qmask;
    p.Wth1 = Wth1; p.bth1 = bth1; p.Wth2 = Wth2; p.bth2 = bth2;
    p.bal  = bal;
    p.gt   = (const float*)d_in[19]; p.bet  = (const float*)d_in[20];
    p.rmt  = (const float*)d_in[21]; p.rvt  = (const float*)d_in[22];
    p.gg   = (const float*)d_in[23]; p.beg  = (const float*)d_in[24];
    p.rmg  = (const float*)d_in[25]; p.rvg  = (const float*)d_in[26];
    p.out  = (float*)d_out;

    k_transpose<<<(BB * MM * CCH + 255) / 256, 256>>>(feat);
    k_knn<<<(BB * NN) / 8, 256>>>(qxyz, sxyz, smask);
    k_compose<<<1, 256>>>(Wg1, Wg2, Wphi, Wpsi, bphi, bpsi, bg1, bg2);

    cudaFuncSetAttribute(k_pre, cudaFuncAttributeMaxDynamicSharedMemorySize,
                         PRE_SM * 4);
    k_pre<<<(BB * MM) / 32, 256, PRE_SM * 4>>>(Wal);

    cudaFuncSetAttribute(k_main, cudaFuncAttributeMaxDynamicSharedMemorySize,
                         SMEM_FLOATS * 4);
    int dev = 0, nsm = 148;
    cudaGetDevice(&dev);
    cudaDeviceGetAttribute(&nsm, cudaDevAttrMultiProcessorCount, dev);
    k_main<<<2 * nsm, 512, SMEM_FLOATS * 4>>>(p);
}